// round 4
// baseline (speedup 1.0000x reference)
#include <cuda_runtime.h>
#include <math.h>

// ---------------- problem constants ----------------
#define FDIM   128
#define HID    64
#define MSZ    64
#define NBATCH 8
#define NPTS   65536          // per batch
#define HH     56
#define WW     56
#define HWSZ   (HH*WW)        // 3136

// scratch: F1[b][h][w][j] = sum_c features[b][c][h][w] * W1[c][j]   (img part of layer 1)
__device__ float g_F1[NBATCH * HWSZ * HID];   // 6.4 MB

typedef unsigned long long ull;

__device__ __forceinline__ ull ffma2(ull a, ull b, ull c) {
    ull d;
    asm("fma.rn.f32x2 %0, %1, %2, %3;" : "=l"(d) : "l"(a), "l"(b), "l"(c));
    return d;
}
__device__ __forceinline__ ull pack2(float lo, float hi) {
    ull r;
    asm("mov.b64 %0, {%1, %2};" : "=l"(r) : "f"(lo), "f"(hi));
    return r;
}
__device__ __forceinline__ float2 unpack2(ull v) {
    float2 r;
    asm("mov.b64 {%0, %1}, %2;" : "=f"(r.x), "=f"(r.y) : "l"(v));
    return r;
}

// ======================================================================
// Kernel 1: precompute F1 = features @ W1_img  (per pixel, 64 outputs)
// grid: 196 blocks x 128 threads = 25088 = NBATCH*HWSZ exactly
// ======================================================================
__global__ void __launch_bounds__(128) k_precompute(const float* __restrict__ features,
                                                    const float* __restrict__ W1g) {
    __shared__ float sW[FDIM * HID];          // 32 KB, rows 0..127 of W1
    int tid = threadIdx.x;
    for (int i = tid; i < FDIM * HID; i += 128) sW[i] = W1g[i];
    __syncthreads();

    int pix = blockIdx.x * 128 + tid;         // < 25088
    int b  = pix / HWSZ;
    int hw = pix % HWSZ;

    ull acc[32];
#pragma unroll
    for (int i = 0; i < 32; i++) acc[i] = 0ull;   // bits of (0.f,0.f)

    const float* fptr = features + (size_t)b * FDIM * HWSZ + hw;
    for (int c = 0; c < FDIM; c++) {
        float f = __ldg(fptr + c * HWSZ);
        ull fp = pack2(f, f);
        const ulonglong2* row = (const ulonglong2*)(sW + c * HID);
#pragma unroll
        for (int jj = 0; jj < 16; jj++) {
            ulonglong2 w = row[jj];
            acc[2*jj]   = ffma2(fp, w.x, acc[2*jj]);
            acc[2*jj+1] = ffma2(fp, w.y, acc[2*jj+1]);
        }
    }
    ulonglong2* dst = (ulonglong2*)(g_F1 + (size_t)pix * HID);
#pragma unroll
    for (int jj = 0; jj < 16; jj++) {
        ulonglong2 v; v.x = acc[2*jj]; v.y = acc[2*jj+1];
        dst[jj] = v;
    }
}

// ======================================================================
// Kernel 2: fused decoder. 1 point per thread, 512-thread CTA (16 warps/SM),
// f32x2 packed MLP, <=128 regs/thread via __launch_bounds__(512,1).
// ======================================================================
#define NT 512
// shared-memory float offsets
#define OFF_W1F 0                 // 128 x 64 : [sin rows 0..63][cos rows 64..127]
#define OFF_W2  8192              // 64 x 64
#define OFF_W3  12288             // 64 x 64
#define OFF_W4  16384             // 64
#define OFF_B1  16448
#define OFF_B2  16512
#define OFF_B3  16576
#define OFF_BG  16640             // 64 x 3
#define OFF_ACT 16832             // 64 rows x NT cols (one column per thread)
#define SMEM_FLOATS (OFF_ACT + 64 * NT)
#define SMEM_BYTES  (SMEM_FLOATS * 4)      // 198400 B -> 1 CTA/SM, 16 warps

// one bilinear tap: acc[0..31] += wt * F1[tap]
#define TAP(IX, IY, WT) {                                                              \
    int _cx = min(max((IX), 0), WW-1), _cy = min(max((IY), 0), HH-1);                  \
    float _w = (((IX) >= 0 && (IX) < WW && (IY) >= 0 && (IY) < HH) ? (WT) : 0.f);      \
    ull _wp = pack2(_w, _w);                                                           \
    const ulonglong2* _src = (const ulonglong2*)(g_F1 + (f1base + (_cy*WW+_cx)*HID));  \
    _Pragma("unroll")                                                                  \
    for (int jj = 0; jj < 16; jj++) {                                                  \
        ulonglong2 _v = _src[jj];                                                      \
        acc[2*jj]   = ffma2(_wp, _v.x, acc[2*jj]);                                     \
        acc[2*jj+1] = ffma2(_wp, _v.y, acc[2*jj+1]);                                   \
    }                                                                                  \
}

// projection + bilinear sample for the thread's point
#define BILIN(PX, PY, PZ) do {                                                         \
    float cx = r0*(PX) + r1*(PY) + r2 *(PZ) + r3;                                      \
    float cy = r4*(PX) + r5*(PY) + r6 *(PZ) + r7;                                      \
    float cz = r8*(PX) + r9*(PY) + r10*(PZ) + r11;                                     \
    float ix = k0*cx + k1*cy + k2*cz;                                                  \
    float iy = k3*cx + k4*cy + k5*cz;                                                  \
    float iz = k6*cx + k7*cy + k8*cz;                                                  \
    float zz = iz + 1e-8f;                                                             \
    float u = ix / zz, v = iy / zz;                                                    \
    float valid = (iz > 0.f) ? 1.f : 0.f;                                              \
    float un = (2.f*u + 1.f) / (float)WW - 1.f;                                        \
    float vn = (2.f*v + 1.f) / (float)HH - 1.f;                                        \
    float xx = ((un + 1.f) * (float)WW - 1.f) * 0.5f;                                  \
    float yy = ((vn + 1.f) * (float)HH - 1.f) * 0.5f;                                  \
    float xf = floorf(xx), yf = floorf(yy);                                            \
    float fx = xx - xf, fy = yy - yf;                                                  \
    int x0i = (int)xf, y0i = (int)yf;                                                  \
    TAP(x0i,     y0i,     (1.f-fx)*(1.f-fy)*valid)                                     \
    TAP(x0i + 1, y0i,     fx      *(1.f-fy)*valid)                                     \
    TAP(x0i,     y0i + 1, (1.f-fx)*fy      *valid)                                     \
    TAP(x0i + 1, y0i + 1, fx      *fy      *valid)                                     \
} while (0)

// relu + store acc to the thread's smem activation column (stride NT, conflict-free)
#define STORE_RELU() {                                                                 \
    _Pragma("unroll")                                                                  \
    for (int i = 0; i < 32; i++) {                                                     \
        float2 f = unpack2(acc[i]);                                                    \
        actc[(2*i)   * NT] = fmaxf(f.x, 0.f);                                          \
        actc[(2*i+1) * NT] = fmaxf(f.y, 0.f);                                          \
    }                                                                                  \
}

// 64x64 dense layer from staging buffer (weight rows broadcast via LDS)
#define LAYER(WOFF, BOFF) {                                                            \
    const ulonglong2* _bv = (const ulonglong2*)(sm + (BOFF));                          \
    _Pragma("unroll")                                                                  \
    for (int jj = 0; jj < 16; jj++) {                                                  \
        ulonglong2 _v = _bv[jj];                                                       \
        acc[2*jj] = _v.x;  acc[2*jj+1] = _v.y;                                         \
    }                                                                                  \
    _Pragma("unroll 4")                                                                \
    for (int kk = 0; kk < 64; kk++) {                                                  \
        float a0 = actc[kk * NT];                                                      \
        ull a0p = pack2(a0, a0);                                                       \
        const ulonglong2* _row = (const ulonglong2*)(sm + (WOFF) + kk * 64);           \
        _Pragma("unroll")                                                              \
        for (int jj = 0; jj < 16; jj++) {                                              \
            ulonglong2 w = _row[jj];                                                   \
            acc[2*jj]   = ffma2(a0p, w.x, acc[2*jj]);                                  \
            acc[2*jj+1] = ffma2(a0p, w.y, acc[2*jj+1]);                                \
        }                                                                              \
    }                                                                                  \
}

__global__ void __launch_bounds__(NT, 1) k_decoder(
    const float* __restrict__ pts, const float* __restrict__ Km,
    const float* __restrict__ RTg, const float* __restrict__ Bgg,
    const float* __restrict__ W1g, const float* __restrict__ b1g,
    const float* __restrict__ W2g, const float* __restrict__ b2g,
    const float* __restrict__ W3g, const float* __restrict__ b3g,
    const float* __restrict__ W4g, const float* __restrict__ b4g,
    float* __restrict__ out)
{
    extern __shared__ float sm[];
    int tid = threadIdx.x;

    // cooperative weight load (W1 rows 128..255 = [sin;cos] block, contiguous)
    for (int i = tid; i < 8192; i += NT) sm[OFF_W1F + i] = W1g[8192 + i];
    for (int i = tid; i < 4096; i += NT) sm[OFF_W2 + i] = W2g[i];
    for (int i = tid; i < 4096; i += NT) sm[OFF_W3 + i] = W3g[i];
    for (int i = tid; i < 64;   i += NT) {
        sm[OFF_W4 + i] = W4g[i];
        sm[OFF_B1 + i] = b1g[i];
        sm[OFF_B2 + i] = b2g[i];
        sm[OFF_B3 + i] = b3g[i];
    }
    for (int i = tid; i < 192; i += NT) sm[OFF_BG + i] = Bgg[i];
    __syncthreads();

    int p0 = blockIdx.x * NT + tid;            // this thread's point (65536 % 512 == 0)
    int bIdx = p0 >> 16;                       // batch index (uniform per block)
    int f1base = bIdx * (HWSZ * HID);

    // camera matrices (uniform across block -> L1 broadcast)
    const float* rtb = RTg + bIdx * 12;
    const float* kb  = Km  + bIdx * 9;
    float r0 = rtb[0], r1 = rtb[1], r2 = rtb[2],  r3 = rtb[3];
    float r4 = rtb[4], r5 = rtb[5], r6 = rtb[6],  r7 = rtb[7];
    float r8 = rtb[8], r9 = rtb[9], r10 = rtb[10], r11 = rtb[11];
    float k0 = kb[0], k1 = kb[1], k2 = kb[2];
    float k3 = kb[3], k4 = kb[4], k5 = kb[5];
    float k6 = kb[6], k7 = kb[7], k8 = kb[8];

    const float* pp0 = pts + (size_t)p0 * 3;
    float px0 = pp0[0], py0 = pp0[1], pz0 = pp0[2];

    // ---- layer 1: acc = b1 + bilinear(F1) + fourier @ W1f ----
    ull acc[32];                               // acc[i] = outputs (2i, 2i+1) packed
    {
        const ulonglong2* bv = (const ulonglong2*)(sm + OFF_B1);
#pragma unroll
        for (int jj = 0; jj < 16; jj++) {
            ulonglong2 v = bv[jj];
            acc[2*jj] = v.x;  acc[2*jj+1] = v.y;
        }
    }

    BILIN(px0, py0, pz0);

    // fourier features: theta_m = 2*pi*(p . Bg[m]); sin/cos via sincospif(2t)
    const float* bg = sm + OFF_BG;
#pragma unroll 4
    for (int m = 0; m < 64; m++) {
        float g0 = bg[3*m], g1 = bg[3*m+1], g2 = bg[3*m+2];
        float t0 = px0*g0 + py0*g1 + pz0*g2;
        float s0, c0;
        sincospif(2.f * t0, &s0, &c0);
        ull s0p = pack2(s0, s0), c0p = pack2(c0, c0);
        const ulonglong2* rs = (const ulonglong2*)(sm + OFF_W1F + m * 64);
        const ulonglong2* rc = (const ulonglong2*)(sm + OFF_W1F + (64 + m) * 64);
#pragma unroll
        for (int jj = 0; jj < 16; jj++) {
            ulonglong2 ws = rs[jj];
            ulonglong2 wc = rc[jj];
            acc[2*jj]   = ffma2(s0p, ws.x, acc[2*jj]);
            acc[2*jj+1] = ffma2(s0p, ws.y, acc[2*jj+1]);
            acc[2*jj]   = ffma2(c0p, wc.x, acc[2*jj]);
            acc[2*jj+1] = ffma2(c0p, wc.y, acc[2*jj+1]);
        }
    }

    float* actc = sm + OFF_ACT + tid;          // thread-private column, stride NT

    STORE_RELU();          // h1 -> staging
    LAYER(OFF_W2, OFF_B2); // h2 = h1 @ W2 + b2
    STORE_RELU();          // h2 -> staging (own column only: no sync needed)
    LAYER(OFF_W3, OFF_B3); // h3 = h2 @ W3 + b3

    // final: relu(h3) . W4 + b4, h3 stays in registers
    float bias4 = __ldg(b4g);
    const float* w4 = sm + OFF_W4;
    float o0 = 0.f;
#pragma unroll
    for (int i = 0; i < 32; i++) {
        float2 a = unpack2(acc[i]);
        o0 += fmaxf(a.x, 0.f) * w4[2*i] + fmaxf(a.y, 0.f) * w4[2*i+1];
    }
    out[p0] = o0 + bias4;
}

// ======================================================================
extern "C" void kernel_launch(void* const* d_in, const int* in_sizes, int n_in,
                              void* d_out, int out_size) {
    const float* features = (const float*)d_in[0];
    const float* points   = (const float*)d_in[1];
    const float* kmat     = (const float*)d_in[2];
    const float* rt       = (const float*)d_in[3];
    const float* Bg       = (const float*)d_in[4];
    const float* W1       = (const float*)d_in[5];
    const float* b1       = (const float*)d_in[6];
    const float* W2       = (const float*)d_in[7];
    const float* b2       = (const float*)d_in[8];
    const float* W3       = (const float*)d_in[9];
    const float* b3       = (const float*)d_in[10];
    const float* W4       = (const float*)d_in[11];
    const float* b4       = (const float*)d_in[12];
    float* out = (float*)d_out;

    cudaFuncSetAttribute(k_decoder, cudaFuncAttributeMaxDynamicSharedMemorySize, SMEM_BYTES);

    k_precompute<<<196, 128>>>(features, W1);
    k_decoder<<<(NBATCH * NPTS) / NT, NT, SMEM_BYTES>>>(
        points, kmat, rt, Bg, W1, b1, W2, b2, W3, b3, W4, b4, out);
}

// round 7
// speedup vs baseline: 1.1464x; 1.1464x over previous
#include <cuda_runtime.h>
#include <math.h>

// ---------------- problem constants ----------------
#define FDIM   128
#define HID    64
#define MSZ    64
#define NBATCH 8
#define NPTS   65536          // per batch
#define HH     56
#define WW     56
#define HWSZ   (HH*WW)        // 3136

// scratch: F1[b][h][w][j] = sum_c features[b][c][h][w] * W1[c][j]   (img part of layer 1)
__device__ float g_F1[NBATCH * HWSZ * HID];   // 6.4 MB

typedef unsigned long long ull;

__device__ __forceinline__ ull ffma2(ull a, ull b, ull c) {
    ull d;
    asm("fma.rn.f32x2 %0, %1, %2, %3;" : "=l"(d) : "l"(a), "l"(b), "l"(c));
    return d;
}
__device__ __forceinline__ ull pack2(float lo, float hi) {
    ull r;
    asm("mov.b64 %0, {%1, %2};" : "=l"(r) : "f"(lo), "f"(hi));
    return r;
}
__device__ __forceinline__ float2 unpack2(ull v) {
    float2 r;
    asm("mov.b64 {%0, %1}, %2;" : "=f"(r.x), "=f"(r.y) : "l"(v));
    return r;
}

// ======================================================================
// Kernel 1: precompute F1 = features @ W1_img  (per pixel, 64 outputs)
// ======================================================================
__global__ void __launch_bounds__(128) k_precompute(const float* __restrict__ features,
                                                    const float* __restrict__ W1g) {
    __shared__ float sW[FDIM * HID];          // 32 KB, rows 0..127 of W1
    int tid = threadIdx.x;
    for (int i = tid; i < FDIM * HID; i += 128) sW[i] = W1g[i];
    __syncthreads();

    int pix = blockIdx.x * 128 + tid;         // < 25088
    int b  = pix / HWSZ;
    int hw = pix % HWSZ;

    ull acc[32];
#pragma unroll
    for (int i = 0; i < 32; i++) acc[i] = 0ull;

    const float* fptr = features + (size_t)b * FDIM * HWSZ + hw;
    for (int c = 0; c < FDIM; c++) {
        float f = __ldg(fptr + c * HWSZ);
        ull fp = pack2(f, f);
        const ulonglong2* row = (const ulonglong2*)(sW + c * HID);
#pragma unroll
        for (int jj = 0; jj < 16; jj++) {
            ulonglong2 w = row[jj];
            acc[2*jj]   = ffma2(fp, w.x, acc[2*jj]);
            acc[2*jj+1] = ffma2(fp, w.y, acc[2*jj+1]);
        }
    }
    ulonglong2* dst = (ulonglong2*)(g_F1 + (size_t)pix * HID);
#pragma unroll
    for (int jj = 0; jj < 16; jj++) {
        ulonglong2 v; v.x = acc[2*jj]; v.y = acc[2*jj+1];
        dst[jj] = v;
    }
}

// ======================================================================
// Kernel 2: fused decoder, j-split design.
//   NT=256 threads; thread pair (t, t+128) covers one set of 128 points.
//   Each thread: 4 points x 32 outputs (its j-half). 8 ffma2 per LDS.128.
// ======================================================================
#define NT  256
#define PT  4                     // points per thread
#define PPC 512                   // points per CTA = 128 lanes * 4
// shared-memory float offsets
#define OFF_W1F 0                 // 128 x 64 : [sin rows 0..63][cos rows 64..127]
#define OFF_W2  8192              // 64 x 64
#define OFF_W3  12288             // 64 x 64
#define OFF_W4  16384             // 64
#define OFF_B1  16448
#define OFF_B2  16512
#define OFF_B3  16576
#define OFF_BG  16640             // 64 x 3
#define OFF_ACT 16832             // 64 rows x 512 cols (col = point slot)
#define SMEM_FLOATS (OFF_ACT + 64 * PPC)
#define SMEM_BYTES  (SMEM_FLOATS * 4)      // 198400 B -> 1 CTA/SM, 8 warps

// load bias half into all 4 point-accumulator sets
#define INIT_BIAS(BOFF) {                                                              \
    const ulonglong2* _bv = (const ulonglong2*)(sm + (BOFF) + jbase);                  \
    _Pragma("unroll")                                                                  \
    for (int q = 0; q < 8; q++) {                                                      \
        ulonglong2 _v = _bv[q];                                                        \
        _Pragma("unroll")                                                              \
        for (int i = 0; i < PT; i++) {                                                 \
            acc[i*16 + 2*q]     = _v.x;                                                \
            acc[i*16 + 2*q + 1] = _v.y;                                                \
        }                                                                              \
    }                                                                                  \
}

// one bilinear tap for point i: acc[i*16..] += wt * F1[tap][jbase..jbase+32)
#define TAP(I, IX, IY, WT) {                                                           \
    int _cx = min(max((IX), 0), WW-1), _cy = min(max((IY), 0), HH-1);                  \
    float _w = (((IX) >= 0 && (IX) < WW && (IY) >= 0 && (IY) < HH) ? (WT) : 0.f);      \
    ull _wp = pack2(_w, _w);                                                           \
    const ulonglong2* _src = (const ulonglong2*)(g_F1 + (f1base + (_cy*WW+_cx)*HID + jbase)); \
    _Pragma("unroll")                                                                  \
    for (int q = 0; q < 8; q++) {                                                      \
        ulonglong2 _v = _src[q];                                                       \
        acc[(I)*16 + 2*q]     = ffma2(_wp, _v.x, acc[(I)*16 + 2*q]);                   \
        acc[(I)*16 + 2*q + 1] = ffma2(_wp, _v.y, acc[(I)*16 + 2*q + 1]);               \
    }                                                                                  \
}

// projection + bilinear sample for point i
#define BILIN(I) do {                                                                  \
    float _px = px[I], _py = py[I], _pz = pz[I];                                       \
    float cx = r0*_px + r1*_py + r2 *_pz + r3;                                         \
    float cy = r4*_px + r5*_py + r6 *_pz + r7;                                         \
    float cz = r8*_px + r9*_py + r10*_pz + r11;                                        \
    float ix = k0*cx + k1*cy + k2*cz;                                                  \
    float iy = k3*cx + k4*cy + k5*cz;                                                  \
    float iz = k6*cx + k7*cy + k8*cz;                                                  \
    float zz = iz + 1e-8f;                                                             \
    float u = ix / zz, v = iy / zz;                                                    \
    float valid = (iz > 0.f) ? 1.f : 0.f;                                              \
    float un = (2.f*u + 1.f) / (float)WW - 1.f;                                        \
    float vn = (2.f*v + 1.f) / (float)HH - 1.f;                                        \
    float xx = ((un + 1.f) * (float)WW - 1.f) * 0.5f;                                  \
    float yy = ((vn + 1.f) * (float)HH - 1.f) * 0.5f;                                  \
    float xf = floorf(xx), yf = floorf(yy);                                            \
    float fx = xx - xf, fy = yy - yf;                                                  \
    int x0i = (int)xf, y0i = (int)yf;                                                  \
    TAP(I, x0i,     y0i,     (1.f-fx)*(1.f-fy)*valid)                                  \
    TAP(I, x0i + 1, y0i,     fx      *(1.f-fy)*valid)                                  \
    TAP(I, x0i,     y0i + 1, (1.f-fx)*fy      *valid)                                  \
    TAP(I, x0i + 1, y0i + 1, fx      *fy      *valid)                                  \
} while (0)

// relu + store this thread's 32 outputs for its 4 points into staging
// row j in [jbase, jbase+32), col = lh + 128*i  (warp lanes consecutive -> no conflicts)
#define STORE_RELU() {                                                                 \
    _Pragma("unroll")                                                                  \
    for (int q = 0; q < 16; q++) {                                                     \
        _Pragma("unroll")                                                              \
        for (int i = 0; i < PT; i++) {                                                 \
            float2 f = unpack2(acc[i*16 + q]);                                         \
            sm[OFF_ACT + (jbase + 2*q)     * PPC + lh + 128*i] = fmaxf(f.x, 0.f);      \
            sm[OFF_ACT + (jbase + 2*q + 1) * PPC + lh + 128*i] = fmaxf(f.y, 0.f);      \
        }                                                                              \
    }                                                                                  \
}

// 64(k) x 32(j-half) dense layer for 4 points; 8 ffma2 per weight LDS.128
#define LAYER(WOFF, BOFF) {                                                            \
    INIT_BIAS(BOFF)                                                                    \
    _Pragma("unroll 2")                                                                \
    for (int kk = 0; kk < 64; kk++) {                                                  \
        ull ap[PT];                                                                    \
        _Pragma("unroll")                                                              \
        for (int i = 0; i < PT; i++) {                                                 \
            float a = sm[OFF_ACT + kk * PPC + lh + 128*i];                             \
            ap[i] = pack2(a, a);                                                       \
        }                                                                              \
        const ulonglong2* _row = (const ulonglong2*)(sm + (WOFF) + kk * 64 + jbase);   \
        _Pragma("unroll")                                                              \
        for (int q = 0; q < 8; q++) {                                                  \
            ulonglong2 w = _row[q];                                                    \
            _Pragma("unroll")                                                          \
            for (int i = 0; i < PT; i++) {                                             \
                acc[i*16 + 2*q]     = ffma2(ap[i], w.x, acc[i*16 + 2*q]);              \
                acc[i*16 + 2*q + 1] = ffma2(ap[i], w.y, acc[i*16 + 2*q + 1]);          \
            }                                                                          \
        }                                                                              \
    }                                                                                  \
}

__global__ void __launch_bounds__(NT, 1) k_decoder(
    const float* __restrict__ pts, const float* __restrict__ Km,
    const float* __restrict__ RTg, const float* __restrict__ Bgg,
    const float* __restrict__ W1g, const float* __restrict__ b1g,
    const float* __restrict__ W2g, const float* __restrict__ b2g,
    const float* __restrict__ W3g, const float* __restrict__ b3g,
    const float* __restrict__ W4g, const float* __restrict__ b4g,
    float* __restrict__ out)
{
    extern __shared__ float sm[];
    int tid = threadIdx.x;
    int jh    = tid >> 7;         // 0 or 1: which 32-output half
    int lh    = tid & 127;        // lane within half = point-slot base
    int jbase = jh * 32;

    // cooperative weight load (W1 rows 128..255 = [sin;cos] block, contiguous)
    for (int i = tid; i < 8192; i += NT) sm[OFF_W1F + i] = W1g[8192 + i];
    for (int i = tid; i < 4096; i += NT) sm[OFF_W2 + i] = W2g[i];
    for (int i = tid; i < 4096; i += NT) sm[OFF_W3 + i] = W3g[i];
    for (int i = tid; i < 64;   i += NT) {
        sm[OFF_W4 + i] = W4g[i];
        sm[OFF_B1 + i] = b1g[i];
        sm[OFF_B2 + i] = b2g[i];
        sm[OFF_B3 + i] = b3g[i];
    }
    for (int i = tid; i < 192; i += NT) sm[OFF_BG + i] = Bgg[i];
    __syncthreads();

    int pbase = blockIdx.x * PPC + lh;         // points: pbase + 128*i, i=0..3
    int bIdx  = (blockIdx.x * PPC) >> 16;      // batch (PPC divides 65536)
    int f1base = bIdx * (HWSZ * HID);

    // camera matrices (uniform across block -> L1 broadcast)
    const float* rtb = RTg + bIdx * 12;
    const float* kb  = Km  + bIdx * 9;
    float r0 = rtb[0], r1 = rtb[1], r2 = rtb[2],  r3 = rtb[3];
    float r4 = rtb[4], r5 = rtb[5], r6 = rtb[6],  r7 = rtb[7];
    float r8 = rtb[8], r9 = rtb[9], r10 = rtb[10], r11 = rtb[11];
    float k0 = kb[0], k1 = kb[1], k2 = kb[2];
    float k3 = kb[3], k4 = kb[4], k5 = kb[5];
    float k6 = kb[6], k7 = kb[7], k8 = kb[8];

    float px[PT], py[PT], pz[PT];
#pragma unroll
    for (int i = 0; i < PT; i++) {
        const float* pp = pts + (size_t)(pbase + 128*i) * 3;
        px[i] = pp[0]; py[i] = pp[1]; pz[i] = pp[2];
    }

    // ---- layer 1: acc = b1 + bilinear(F1) + fourier @ W1f  (j-half only) ----
    ull acc[64];                   // acc[i*16 + q]: point i, outputs (jbase+2q, +1)
    INIT_BIAS(OFF_B1)

    BILIN(0); BILIN(1); BILIN(2); BILIN(3);

    // fourier features
    const float* bg = sm + OFF_BG;
#pragma unroll 1
    for (int m = 0; m < 64; m++) {
        float g0 = bg[3*m], g1 = bg[3*m+1], g2 = bg[3*m+2];
        ull sp[PT], cp[PT];
#pragma unroll
        for (int i = 0; i < PT; i++) {
            float t = px[i]*g0 + py[i]*g1 + pz[i]*g2;
            float s, c;
            sincospif(2.f * t, &s, &c);
            sp[i] = pack2(s, s); cp[i] = pack2(c, c);
        }
        const ulonglong2* rs = (const ulonglong2*)(sm + OFF_W1F + m * 64 + jbase);
        const ulonglong2* rc = (const ulonglong2*)(sm + OFF_W1F + (64 + m) * 64 + jbase);
#pragma unroll
        for (int q = 0; q < 8; q++) {
            ulonglong2 ws = rs[q];
            ulonglong2 wc = rc[q];
#pragma unroll
            for (int i = 0; i < PT; i++) {
                acc[i*16 + 2*q]     = ffma2(sp[i], ws.x, acc[i*16 + 2*q]);
                acc[i*16 + 2*q + 1] = ffma2(sp[i], ws.y, acc[i*16 + 2*q + 1]);
                acc[i*16 + 2*q]     = ffma2(cp[i], wc.x, acc[i*16 + 2*q]);
                acc[i*16 + 2*q + 1] = ffma2(cp[i], wc.y, acc[i*16 + 2*q + 1]);
            }
        }
    }

    STORE_RELU();                 // h1 (this j-half) -> staging
    __syncthreads();              // partner half must land before layer reads all k
    LAYER(OFF_W2, OFF_B2);        // h2 = relu(h1) @ W2 + b2   (j-half)
    __syncthreads();              // all reads of h1 staging done
    STORE_RELU();                 // h2 -> staging
    __syncthreads();
    LAYER(OFF_W3, OFF_B3);        // h3 = relu(h2) @ W3 + b3   (j-half)

    // final: partial dot over this j-half, then cross-pair reduction via smem
    const float* w4 = sm + OFF_W4 + jbase;
    float o[PT] = {0.f, 0.f, 0.f, 0.f};
#pragma unroll
    for (int q = 0; q < 16; q++) {
        float wlo = w4[2*q], whi = w4[2*q+1];
#pragma unroll
        for (int i = 0; i < PT; i++) {
            float2 a = unpack2(acc[i*16 + q]);
            o[i] += fmaxf(a.x, 0.f) * wlo + fmaxf(a.y, 0.f) * whi;
        }
    }

    __syncthreads();              // staging free for reduction
    if (jh == 1) {
#pragma unroll
        for (int i = 0; i < PT; i++) sm[OFF_ACT + lh + 128*i] = o[i];
    }
    __syncthreads();
    if (jh == 0) {
        float bias4 = __ldg(b4g);
#pragma unroll
        for (int i = 0; i < PT; i++)
            out[pbase + 128*i] = o[i] + sm[OFF_ACT + lh + 128*i] + bias4;
    }
}

// ======================================================================
extern "C" void kernel_launch(void* const* d_in, const int* in_sizes, int n_in,
                              void* d_out, int out_size) {
    const float* features = (const float*)d_in[0];
    const float* points   = (const float*)d_in[1];
    const float* kmat     = (const float*)d_in[2];
    const float* rt       = (const float*)d_in[3];
    const float* Bg       = (const float*)d_in[4];
    const float* W1       = (const float*)d_in[5];
    const float* b1       = (const float*)d_in[6];
    const float* W2       = (const float*)d_in[7];
    const float* b2       = (const float*)d_in[8];
    const float* W3       = (const float*)d_in[9];
    const float* b3       = (const float*)d_in[10];
    const float* W4       = (const float*)d_in[11];
    const float* b4       = (const float*)d_in[12];
    float* out = (float*)d_out;

    cudaFuncSetAttribute(k_decoder, cudaFuncAttributeMaxDynamicSharedMemorySize, SMEM_BYTES);

    k_precompute<<<196, 128>>>(features, W1);
    k_decoder<<<(NBATCH * NPTS) / PPC, NT, SMEM_BYTES>>>(
        points, kmat, rt, Bg, W1, b1, W2, b2, W3, b3, W4, b4, out);
}

// round 10
// speedup vs baseline: 1.2398x; 1.0815x over previous
#include <cuda_runtime.h>
#include <math.h>

// ---------------- problem constants ----------------
#define FDIM   128
#define HID    64
#define MSZ    64
#define NBATCH 8
#define NPTS   65536          // per batch
#define HH     56
#define WW     56
#define HWSZ   (HH*WW)        // 3136

// scratch: F1[b][h][w][j] = sum_c features[b][c][h][w] * W1[c][j]   (img part of layer 1)
__device__ float g_F1[NBATCH * HWSZ * HID];   // 6.4 MB

typedef unsigned long long ull;

__device__ __forceinline__ ull ffma2(ull a, ull b, ull c) {
    ull d;
    asm("fma.rn.f32x2 %0, %1, %2, %3;" : "=l"(d) : "l"(a), "l"(b), "l"(c));
    return d;
}
__device__ __forceinline__ ull pack2(float lo, float hi) {
    ull r;
    asm("mov.b64 %0, {%1, %2};" : "=l"(r) : "f"(lo), "f"(hi));
    return r;
}
__device__ __forceinline__ float2 unpack2(ull v) {
    float2 r;
    asm("mov.b64 {%0, %1}, %2;" : "=f"(r.x), "=f"(r.y) : "l"(v));
    return r;
}

// fast, accurate sin/cos of 2*pi*t:
//   f = t - rint(t) in [-0.5, 0.5]  (exact), then MUFU sin/cos of 2*pi*f in [-pi, pi]
__device__ __forceinline__ void sincos_2pi(float t, float* s, float* c) {
    float f = t - rintf(t);
    float ang = 6.2831853071795865f * f;
    float ss, cc;
    asm("sin.approx.f32 %0, %1;" : "=f"(ss) : "f"(ang));
    asm("cos.approx.f32 %0, %1;" : "=f"(cc) : "f"(ang));
    *s = ss; *c = cc;
}

// ======================================================================
// Kernel 1: precompute F1 = features @ W1_img  (per pixel, 64 outputs)
// ======================================================================
__global__ void __launch_bounds__(128) k_precompute(const float* __restrict__ features,
                                                    const float* __restrict__ W1g) {
    __shared__ float sW[FDIM * HID];          // 32 KB, rows 0..127 of W1
    int tid = threadIdx.x;
    for (int i = tid; i < FDIM * HID; i += 128) sW[i] = W1g[i];
    __syncthreads();

    int pix = blockIdx.x * 128 + tid;         // < 25088
    int b  = pix / HWSZ;
    int hw = pix % HWSZ;

    ull acc[32];
#pragma unroll
    for (int i = 0; i < 32; i++) acc[i] = 0ull;

    const float* fptr = features + (size_t)b * FDIM * HWSZ + hw;
    for (int c = 0; c < FDIM; c++) {
        float f = __ldg(fptr + c * HWSZ);
        ull fp = pack2(f, f);
        const ulonglong2* row = (const ulonglong2*)(sW + c * HID);
#pragma unroll
        for (int jj = 0; jj < 16; jj++) {
            ulonglong2 w = row[jj];
            acc[2*jj]   = ffma2(fp, w.x, acc[2*jj]);
            acc[2*jj+1] = ffma2(fp, w.y, acc[2*jj+1]);
        }
    }
    ulonglong2* dst = (ulonglong2*)(g_F1 + (size_t)pix * HID);
#pragma unroll
    for (int jj = 0; jj < 16; jj++) {
        ulonglong2 v; v.x = acc[2*jj]; v.y = acc[2*jj+1];
        dst[jj] = v;
    }
}

// ======================================================================
// Kernel 2: fused decoder, j-split design.
//   NT=256 threads; thread pair (t, t+128) covers one set of 128 points.
//   Each thread: 4 points x 32 outputs (its j-half). 8 ffma2 per LDS.128.
// ======================================================================
#define NT  256
#define PT  4                     // points per thread
#define PPC 512                   // points per CTA = 128 lanes * 4
// shared-memory float offsets
#define OFF_W1F 0                 // 128 x 64 : [sin rows 0..63][cos rows 64..127]
#define OFF_W2  8192              // 64 x 64
#define OFF_W3  12288             // 64 x 64
#define OFF_W4  16384             // 64
#define OFF_B1  16448
#define OFF_B2  16512
#define OFF_B3  16576
#define OFF_BG  16640             // 64 x 3
#define OFF_ACT 16832             // 64 rows x 512 cols (col = point slot)
#define SMEM_FLOATS (OFF_ACT + 64 * PPC)
#define SMEM_BYTES  (SMEM_FLOATS * 4)      // 198400 B -> 1 CTA/SM, 8 warps

// load bias half into all 4 point-accumulator sets
#define INIT_BIAS(BOFF) {                                                              \
    const ulonglong2* _bv = (const ulonglong2*)(sm + (BOFF) + jbase);                  \
    _Pragma("unroll")                                                                  \
    for (int q = 0; q < 8; q++) {                                                      \
        ulonglong2 _v = _bv[q];                                                        \
        _Pragma("unroll")                                                              \
        for (int i = 0; i < PT; i++) {                                                 \
            acc[i*16 + 2*q]     = _v.x;                                                \
            acc[i*16 + 2*q + 1] = _v.y;                                                \
        }                                                                              \
    }                                                                                  \
}

// one bilinear tap for point i: acc[i*16..] += wt * F1[tap][jbase..jbase+32)
#define TAP(I, IX, IY, WT) {                                                           \
    int _cx = min(max((IX), 0), WW-1), _cy = min(max((IY), 0), HH-1);                  \
    float _w = (((IX) >= 0 && (IX) < WW && (IY) >= 0 && (IY) < HH) ? (WT) : 0.f);      \
    ull _wp = pack2(_w, _w);                                                           \
    const ulonglong2* _src = (const ulonglong2*)(g_F1 + (f1base + (_cy*WW+_cx)*HID + jbase)); \
    _Pragma("unroll")                                                                  \
    for (int q = 0; q < 8; q++) {                                                      \
        ulonglong2 _v = _src[q];                                                       \
        acc[(I)*16 + 2*q]     = ffma2(_wp, _v.x, acc[(I)*16 + 2*q]);                   \
        acc[(I)*16 + 2*q + 1] = ffma2(_wp, _v.y, acc[(I)*16 + 2*q + 1]);               \
    }                                                                                  \
}

// projection + bilinear sample for point i
#define BILIN(I) do {                                                                  \
    float _px = px[I], _py = py[I], _pz = pz[I];                                       \
    float cx = r0*_px + r1*_py + r2 *_pz + r3;                                         \
    float cy = r4*_px + r5*_py + r6 *_pz + r7;                                         \
    float cz = r8*_px + r9*_py + r10*_pz + r11;                                        \
    float ix = k0*cx + k1*cy + k2*cz;                                                  \
    float iy = k3*cx + k4*cy + k5*cz;                                                  \
    float iz = k6*cx + k7*cy + k8*cz;                                                  \
    float zz = iz + 1e-8f;                                                             \
    float u = ix / zz, v = iy / zz;                                                    \
    float valid = (iz > 0.f) ? 1.f : 0.f;                                              \
    float un = (2.f*u + 1.f) / (float)WW - 1.f;                                        \
    float vn = (2.f*v + 1.f) / (float)HH - 1.f;                                        \
    float xx = ((un + 1.f) * (float)WW - 1.f) * 0.5f;                                  \
    float yy = ((vn + 1.f) * (float)HH - 1.f) * 0.5f;                                  \
    float xf = floorf(xx), yf = floorf(yy);                                            \
    float fx = xx - xf, fy = yy - yf;                                                  \
    int x0i = (int)xf, y0i = (int)yf;                                                  \
    TAP(I, x0i,     y0i,     (1.f-fx)*(1.f-fy)*valid)                                  \
    TAP(I, x0i + 1, y0i,     fx      *(1.f-fy)*valid)                                  \
    TAP(I, x0i,     y0i + 1, (1.f-fx)*fy      *valid)                                  \
    TAP(I, x0i + 1, y0i + 1, fx      *fy      *valid)                                  \
} while (0)

// relu + store this thread's 32 outputs for its 4 points into staging
// row j in [jbase, jbase+32), col = lh + 128*i  (warp lanes consecutive -> no conflicts)
#define STORE_RELU() {                                                                 \
    _Pragma("unroll")                                                                  \
    for (int q = 0; q < 16; q++) {                                                     \
        _Pragma("unroll")                                                              \
        for (int i = 0; i < PT; i++) {                                                 \
            float2 f = unpack2(acc[i*16 + q]);                                         \
            sm[OFF_ACT + (jbase + 2*q)     * PPC + lh + 128*i] = fmaxf(f.x, 0.f);      \
            sm[OFF_ACT + (jbase + 2*q + 1) * PPC + lh + 128*i] = fmaxf(f.y, 0.f);      \
        }                                                                              \
    }                                                                                  \
}

// 64(k) x 32(j-half) dense layer for 4 points; 8 ffma2 per weight LDS.128
#define LAYER(WOFF, BOFF) {                                                            \
    INIT_BIAS(BOFF)                                                                    \
    _Pragma("unroll 2")                                                                \
    for (int kk = 0; kk < 64; kk++) {                                                  \
        ull ap[PT];                                                                    \
        _Pragma("unroll")                                                              \
        for (int i = 0; i < PT; i++) {                                                 \
            float a = sm[OFF_ACT + kk * PPC + lh + 128*i];                             \
            ap[i] = pack2(a, a);                                                       \
        }                                                                              \
        const ulonglong2* _row = (const ulonglong2*)(sm + (WOFF) + kk * 64 + jbase);   \
        _Pragma("unroll")                                                              \
        for (int q = 0; q < 8; q++) {                                                  \
            ulonglong2 w = _row[q];                                                    \
            _Pragma("unroll")                                                          \
            for (int i = 0; i < PT; i++) {                                             \
                acc[i*16 + 2*q]     = ffma2(ap[i], w.x, acc[i*16 + 2*q]);              \
                acc[i*16 + 2*q + 1] = ffma2(ap[i], w.y, acc[i*16 + 2*q + 1]);          \
            }                                                                          \
        }                                                                              \
    }                                                                                  \
}

__global__ void __launch_bounds__(NT, 1) k_decoder(
    const float* __restrict__ pts, const float* __restrict__ Km,
    const float* __restrict__ RTg, const float* __restrict__ Bgg,
    const float* __restrict__ W1g, const float* __restrict__ b1g,
    const float* __restrict__ W2g, const float* __restrict__ b2g,
    const float* __restrict__ W3g, const float* __restrict__ b3g,
    const float* __restrict__ W4g, const float* __restrict__ b4g,
    float* __restrict__ out)
{
    extern __shared__ float sm[];
    int tid = threadIdx.x;
    int jh    = tid >> 7;         // 0 or 1: which 32-output half
    int lh    = tid & 127;        // lane within half = point-slot base
    int jbase = jh * 32;

    // cooperative weight load (W1 rows 128..255 = [sin;cos] block, contiguous)
    for (int i = tid; i < 8192; i += NT) sm[OFF_W1F + i] = W1g[8192 + i];
    for (int i = tid; i < 4096; i += NT) sm[OFF_W2 + i] = W2g[i];
    for (int i = tid; i < 4096; i += NT) sm[OFF_W3 + i] = W3g[i];
    for (int i = tid; i < 64;   i += NT) {
        sm[OFF_W4 + i] = W4g[i];
        sm[OFF_B1 + i] = b1g[i];
        sm[OFF_B2 + i] = b2g[i];
        sm[OFF_B3 + i] = b3g[i];
    }
    for (int i = tid; i < 192; i += NT) sm[OFF_BG + i] = Bgg[i];
    __syncthreads();

    int pbase = blockIdx.x * PPC + lh;         // points: pbase + 128*i, i=0..3
    int bIdx  = (blockIdx.x * PPC) >> 16;      // batch (PPC divides 65536)
    int f1base = bIdx * (HWSZ * HID);

    // camera matrices (uniform across block -> L1 broadcast)
    const float* rtb = RTg + bIdx * 12;
    const float* kb  = Km  + bIdx * 9;
    float r0 = rtb[0], r1 = rtb[1], r2 = rtb[2],  r3 = rtb[3];
    float r4 = rtb[4], r5 = rtb[5], r6 = rtb[6],  r7 = rtb[7];
    float r8 = rtb[8], r9 = rtb[9], r10 = rtb[10], r11 = rtb[11];
    float k0 = kb[0], k1 = kb[1], k2 = kb[2];
    float k3 = kb[3], k4 = kb[4], k5 = kb[5];
    float k6 = kb[6], k7 = kb[7], k8 = kb[8];

    float px[PT], py[PT], pz[PT];
#pragma unroll
    for (int i = 0; i < PT; i++) {
        const float* pp = pts + (size_t)(pbase + 128*i) * 3;
        px[i] = pp[0]; py[i] = pp[1]; pz[i] = pp[2];
    }

    // ---- layer 1: acc = b1 + bilinear(F1) + fourier @ W1f  (j-half only) ----
    ull acc[64];                   // acc[i*16 + q]: point i, outputs (jbase+2q, +1)
    INIT_BIAS(OFF_B1)

    BILIN(0); BILIN(1); BILIN(2); BILIN(3);

    // fourier features: sin/cos(2*pi*(p.Bg_m)) via exact fold + MUFU
    const float* bg = sm + OFF_BG;
#pragma unroll 1
    for (int m = 0; m < 64; m++) {
        float g0 = bg[3*m], g1 = bg[3*m+1], g2 = bg[3*m+2];
        ull sp[PT], cp[PT];
#pragma unroll
        for (int i = 0; i < PT; i++) {
            float t = px[i]*g0 + py[i]*g1 + pz[i]*g2;
            float s, c;
            sincos_2pi(t, &s, &c);
            sp[i] = pack2(s, s); cp[i] = pack2(c, c);
        }
        const ulonglong2* rs = (const ulonglong2*)(sm + OFF_W1F + m * 64 + jbase);
        const ulonglong2* rc = (const ulonglong2*)(sm + OFF_W1F + (64 + m) * 64 + jbase);
#pragma unroll
        for (int q = 0; q < 8; q++) {
            ulonglong2 ws = rs[q];
            ulonglong2 wc = rc[q];
#pragma unroll
            for (int i = 0; i < PT; i++) {
                acc[i*16 + 2*q]     = ffma2(sp[i], ws.x, acc[i*16 + 2*q]);
                acc[i*16 + 2*q + 1] = ffma2(sp[i], ws.y, acc[i*16 + 2*q + 1]);
                acc[i*16 + 2*q]     = ffma2(cp[i], wc.x, acc[i*16 + 2*q]);
                acc[i*16 + 2*q + 1] = ffma2(cp[i], wc.y, acc[i*16 + 2*q + 1]);
            }
        }
    }

    STORE_RELU();                 // h1 (this j-half) -> staging
    __syncthreads();              // partner half must land before layer reads all k
    LAYER(OFF_W2, OFF_B2);        // h2 = relu(h1) @ W2 + b2   (j-half)
    __syncthreads();              // all reads of h1 staging done
    STORE_RELU();                 // h2 -> staging
    __syncthreads();
    LAYER(OFF_W3, OFF_B3);        // h3 = relu(h2) @ W3 + b3   (j-half)

    // final: partial dot over this j-half, then cross-pair reduction via smem
    const float* w4 = sm + OFF_W4 + jbase;
    float o[PT] = {0.f, 0.f, 0.f, 0.f};
#pragma unroll
    for (int q = 0; q < 16; q++) {
        float wlo = w4[2*q], whi = w4[2*q+1];
#pragma unroll
        for (int i = 0; i < PT; i++) {
            float2 a = unpack2(acc[i*16 + q]);
            o[i] += fmaxf(a.x, 0.f) * wlo + fmaxf(a.y, 0.f) * whi;
        }
    }

    __syncthreads();              // staging free for reduction
    if (jh == 1) {
#pragma unroll
        for (int i = 0; i < PT; i++) sm[OFF_ACT + lh + 128*i] = o[i];
    }
    __syncthreads();
    if (jh == 0) {
        float bias4 = __ldg(b4g);
#pragma unroll
        for (int i = 0; i < PT; i++)
            out[pbase + 128*i] = o[i] + sm[OFF_ACT + lh + 128*i] + bias4;
    }
}

// ======================================================================
extern "C" void kernel_launch(void* const* d_in, const int* in_sizes, int n_in,
                              void* d_out, int out_size) {
    const float* features = (const float*)d_in[0];
    const float* points   = (const float*)d_in[1];
    const float* kmat     = (const float*)d_in[2];
    const float* rt       = (const float*)d_in[3];
    const float* Bg       = (const float*)d_in[4];
    const float* W1       = (const float*)d_in[5];
    const float* b1       = (const float*)d_in[6];
    const float* W2       = (const float*)d_in[7];
    const float* b2       = (const float*)d_in[8];
    const float* W3       = (const float*)d_in[9];
    const float* b3       = (const float*)d_in[10];
    const float* W4       = (const float*)d_in[11];
    const float* b4       = (const float*)d_in[12];
    float* out = (float*)d_out;

    cudaFuncSetAttribute(k_decoder, cudaFuncAttributeMaxDynamicSharedMemorySize, SMEM_BYTES);

    k_precompute<<<196, 128>>>(features, W1);
    k_decoder<<<(NBATCH * NPTS) / PPC, NT, SMEM_BYTES>>>(
        points, kmat, rt, Bg, W1, b1, W2, b2, W3, b3, W4, b4, out);
}

// round 11
// speedup vs baseline: 1.2891x; 1.0398x over previous
#include <cuda_runtime.h>
#include <math.h>

// ---------------- problem constants ----------------
#define FDIM   128
#define HID    64
#define MSZ    64
#define NBATCH 8
#define NPTS   65536          // per batch
#define HH     56
#define WW     56
#define HWSZ   (HH*WW)        // 3136

// scratch: F1[b][h][w][j] = sum_c features[b][c][h][w] * W1[c][j]   (img part of layer 1)
__device__ float g_F1[NBATCH * HWSZ * HID];   // 6.4 MB

typedef unsigned long long ull;

__device__ __forceinline__ ull ffma2(ull a, ull b, ull c) {
    ull d;
    asm("fma.rn.f32x2 %0, %1, %2, %3;" : "=l"(d) : "l"(a), "l"(b), "l"(c));
    return d;
}
__device__ __forceinline__ ull pack2(float lo, float hi) {
    ull r;
    asm("mov.b64 %0, {%1, %2};" : "=l"(r) : "f"(lo), "f"(hi));
    return r;
}
__device__ __forceinline__ float2 unpack2(ull v) {
    float2 r;
    asm("mov.b64 {%0, %1}, %2;" : "=f"(r.x), "=f"(r.y) : "l"(v));
    return r;
}

// fast, accurate sin/cos of 2*pi*t:
//   f = t - rint(t) in [-0.5, 0.5]  (exact), then MUFU sin/cos of 2*pi*f in [-pi, pi]
__device__ __forceinline__ void sincos_2pi(float t, float* s, float* c) {
    float f = t - rintf(t);
    float ang = 6.2831853071795865f * f;
    float ss, cc;
    asm("sin.approx.f32 %0, %1;" : "=f"(ss) : "f"(ang));
    asm("cos.approx.f32 %0, %1;" : "=f"(cc) : "f"(ang));
    *s = ss; *c = cc;
}

// ======================================================================
// Kernel 1: precompute F1 = features @ W1_img  (per pixel, 64 outputs)
// ======================================================================
__global__ void __launch_bounds__(128) k_precompute(const float* __restrict__ features,
                                                    const float* __restrict__ W1g) {
    __shared__ float sW[FDIM * HID];          // 32 KB, rows 0..127 of W1
    int tid = threadIdx.x;
    for (int i = tid; i < FDIM * HID; i += 128) sW[i] = W1g[i];
    __syncthreads();

    int pix = blockIdx.x * 128 + tid;         // < 25088
    int b  = pix / HWSZ;
    int hw = pix % HWSZ;

    ull acc[32];
#pragma unroll
    for (int i = 0; i < 32; i++) acc[i] = 0ull;

    const float* fptr = features + (size_t)b * FDIM * HWSZ + hw;
    for (int c = 0; c < FDIM; c++) {
        float f = __ldg(fptr + c * HWSZ);
        ull fp = pack2(f, f);
        const ulonglong2* row = (const ulonglong2*)(sW + c * HID);
#pragma unroll
        for (int jj = 0; jj < 16; jj++) {
            ulonglong2 w = row[jj];
            acc[2*jj]   = ffma2(fp, w.x, acc[2*jj]);
            acc[2*jj+1] = ffma2(fp, w.y, acc[2*jj+1]);
        }
    }
    ulonglong2* dst = (ulonglong2*)(g_F1 + (size_t)pix * HID);
#pragma unroll
    for (int jj = 0; jj < 16; jj++) {
        ulonglong2 v; v.x = acc[2*jj]; v.y = acc[2*jj+1];
        dst[jj] = v;
    }
}

// ======================================================================
// Kernel 2: fused decoder, 4-way j-split.
//   NT=512 threads: 4 j-quarters x 128 lanes. Each thread: 4 points x 16
//   outputs. acc = 32 ull = 64 regs -> fits 128-reg cap, 16 warps/SM.
// ======================================================================
#define NT  512
#define PT  4                     // points per thread
#define PPC 512                   // points per CTA = 128 lanes * 4
// shared-memory float offsets
#define OFF_W1F 0                 // 128 x 64 : [sin rows 0..63][cos rows 64..127]
#define OFF_W2  8192              // 64 x 64
#define OFF_W3  12288             // 64 x 64
#define OFF_W4  16384             // 64
#define OFF_B1  16448
#define OFF_B2  16512
#define OFF_B3  16576
#define OFF_BG  16640             // 64 x 3
#define OFF_ACT 16832             // 64 rows x 512 cols (col = point slot)
#define SMEM_FLOATS (OFF_ACT + 64 * PPC)
#define SMEM_BYTES  (SMEM_FLOATS * 4)      // 198400 B -> 1 CTA/SM, 16 warps

// load this quarter's 16 bias values into all 4 point-accumulator sets
#define INIT_BIAS(BOFF) {                                                              \
    const ulonglong2* _bv = (const ulonglong2*)(sm + (BOFF) + jbase);                  \
    _Pragma("unroll")                                                                  \
    for (int q = 0; q < 4; q++) {                                                      \
        ulonglong2 _v = _bv[q];                                                        \
        _Pragma("unroll")                                                              \
        for (int i = 0; i < PT; i++) {                                                 \
            acc[i*8 + 2*q]     = _v.x;                                                 \
            acc[i*8 + 2*q + 1] = _v.y;                                                 \
        }                                                                              \
    }                                                                                  \
}

// one bilinear tap for point i: acc[i*8..] += wt * F1[tap][jbase..jbase+16)
#define TAP(I, IX, IY, WT) {                                                           \
    int _cx = min(max((IX), 0), WW-1), _cy = min(max((IY), 0), HH-1);                  \
    float _w = (((IX) >= 0 && (IX) < WW && (IY) >= 0 && (IY) < HH) ? (WT) : 0.f);      \
    ull _wp = pack2(_w, _w);                                                           \
    const ulonglong2* _src = (const ulonglong2*)(g_F1 + (f1base + (_cy*WW+_cx)*HID + jbase)); \
    _Pragma("unroll")                                                                  \
    for (int q = 0; q < 4; q++) {                                                      \
        ulonglong2 _v = _src[q];                                                       \
        acc[(I)*8 + 2*q]     = ffma2(_wp, _v.x, acc[(I)*8 + 2*q]);                     \
        acc[(I)*8 + 2*q + 1] = ffma2(_wp, _v.y, acc[(I)*8 + 2*q + 1]);                 \
    }                                                                                  \
}

// projection + bilinear sample for point i (M = K*RT folded, 3x4)
#define BILIN(I) do {                                                                  \
    float _px = px[I], _py = py[I], _pz = pz[I];                                       \
    float ix = m0*_px + m1*_py + m2 *_pz + m3;                                         \
    float iy = m4*_px + m5*_py + m6 *_pz + m7;                                         \
    float iz = m8*_px + m9*_py + m10*_pz + m11;                                        \
    float zz = iz + 1e-8f;                                                             \
    float u = ix / zz, v = iy / zz;                                                    \
    float valid = (iz > 0.f) ? 1.f : 0.f;                                              \
    float un = (2.f*u + 1.f) / (float)WW - 1.f;                                        \
    float vn = (2.f*v + 1.f) / (float)HH - 1.f;                                        \
    float xx = ((un + 1.f) * (float)WW - 1.f) * 0.5f;                                  \
    float yy = ((vn + 1.f) * (float)HH - 1.f) * 0.5f;                                  \
    float xf = floorf(xx), yf = floorf(yy);                                            \
    float fx = xx - xf, fy = yy - yf;                                                  \
    int x0i = (int)xf, y0i = (int)yf;                                                  \
    TAP(I, x0i,     y0i,     (1.f-fx)*(1.f-fy)*valid)                                  \
    TAP(I, x0i + 1, y0i,     fx      *(1.f-fy)*valid)                                  \
    TAP(I, x0i,     y0i + 1, (1.f-fx)*fy      *valid)                                  \
    TAP(I, x0i + 1, y0i + 1, fx      *fy      *valid)                                  \
} while (0)

// relu + store this thread's 16 outputs for its 4 points into staging
// row j in [jbase, jbase+16), col = lh + 128*i (warp lanes consecutive)
#define STORE_RELU() {                                                                 \
    _Pragma("unroll")                                                                  \
    for (int q = 0; q < 8; q++) {                                                      \
        _Pragma("unroll")                                                              \
        for (int i = 0; i < PT; i++) {                                                 \
            float2 f = unpack2(acc[i*8 + q]);                                          \
            sm[OFF_ACT + (jbase + 2*q)     * PPC + lh + 128*i] = fmaxf(f.x, 0.f);      \
            sm[OFF_ACT + (jbase + 2*q + 1) * PPC + lh + 128*i] = fmaxf(f.y, 0.f);      \
        }                                                                              \
    }                                                                                  \
}

// 64(k) x 16(j-quarter) dense layer for 4 points
#define LAYER(WOFF, BOFF) {                                                            \
    INIT_BIAS(BOFF)                                                                    \
    _Pragma("unroll 4")                                                                \
    for (int kk = 0; kk < 64; kk++) {                                                  \
        ull ap[PT];                                                                    \
        _Pragma("unroll")                                                              \
        for (int i = 0; i < PT; i++) {                                                 \
            float a = sm[OFF_ACT + kk * PPC + lh + 128*i];                             \
            ap[i] = pack2(a, a);                                                       \
        }                                                                              \
        const ulonglong2* _row = (const ulonglong2*)(sm + (WOFF) + kk * 64 + jbase);   \
        _Pragma("unroll")                                                              \
        for (int q = 0; q < 4; q++) {                                                  \
            ulonglong2 w = _row[q];                                                    \
            _Pragma("unroll")                                                          \
            for (int i = 0; i < PT; i++) {                                             \
                acc[i*8 + 2*q]     = ffma2(ap[i], w.x, acc[i*8 + 2*q]);                \
                acc[i*8 + 2*q + 1] = ffma2(ap[i], w.y, acc[i*8 + 2*q + 1]);            \
            }                                                                          \
        }                                                                              \
    }                                                                                  \
}

__global__ void __launch_bounds__(NT, 1) k_decoder(
    const float* __restrict__ pts, const float* __restrict__ Km,
    const float* __restrict__ RTg, const float* __restrict__ Bgg,
    const float* __restrict__ W1g, const float* __restrict__ b1g,
    const float* __restrict__ W2g, const float* __restrict__ b2g,
    const float* __restrict__ W3g, const float* __restrict__ b3g,
    const float* __restrict__ W4g, const float* __restrict__ b4g,
    float* __restrict__ out)
{
    extern __shared__ float sm[];
    int tid = threadIdx.x;
    int jq    = tid >> 7;         // 0..3: which 16-output quarter
    int lh    = tid & 127;        // lane within quarter = point-slot base
    int jbase = jq * 16;

    // cooperative weight load (W1 rows 128..255 = [sin;cos] block, contiguous)
    for (int i = tid; i < 8192; i += NT) sm[OFF_W1F + i] = W1g[8192 + i];
    for (int i = tid; i < 4096; i += NT) sm[OFF_W2 + i] = W2g[i];
    for (int i = tid; i < 4096; i += NT) sm[OFF_W3 + i] = W3g[i];
    for (int i = tid; i < 64;   i += NT) {
        sm[OFF_W4 + i] = W4g[i];
        sm[OFF_B1 + i] = b1g[i];
        sm[OFF_B2 + i] = b2g[i];
        sm[OFF_B3 + i] = b3g[i];
    }
    for (int i = tid; i < 192; i += NT) sm[OFF_BG + i] = Bgg[i];
    __syncthreads();

    int pbase = blockIdx.x * PPC + lh;         // points: pbase + 128*i, i=0..3
    int bIdx  = (blockIdx.x * PPC) >> 16;      // batch (PPC divides 65536)
    int f1base = bIdx * (HWSZ * HID);

    // fold camera: M = K @ RT (3x4). Uniform per block -> L1 broadcast.
    float m0, m1, m2, m3, m4, m5, m6, m7, m8, m9, m10, m11;
    {
        const float* rtb = RTg + bIdx * 12;
        const float* kb  = Km  + bIdx * 9;
        float kk0 = kb[0], kk1 = kb[1], kk2 = kb[2];
        float kk3 = kb[3], kk4 = kb[4], kk5 = kb[5];
        float kk6 = kb[6], kk7 = kb[7], kk8 = kb[8];
        m0  = kk0*rtb[0] + kk1*rtb[4] + kk2*rtb[8];
        m1  = kk0*rtb[1] + kk1*rtb[5] + kk2*rtb[9];
        m2  = kk0*rtb[2] + kk1*rtb[6] + kk2*rtb[10];
        m3  = kk0*rtb[3] + kk1*rtb[7] + kk2*rtb[11];
        m4  = kk3*rtb[0] + kk4*rtb[4] + kk5*rtb[8];
        m5  = kk3*rtb[1] + kk4*rtb[5] + kk5*rtb[9];
        m6  = kk3*rtb[2] + kk4*rtb[6] + kk5*rtb[10];
        m7  = kk3*rtb[3] + kk4*rtb[7] + kk5*rtb[11];
        m8  = kk6*rtb[0] + kk7*rtb[4] + kk8*rtb[8];
        m9  = kk6*rtb[1] + kk7*rtb[5] + kk8*rtb[9];
        m10 = kk6*rtb[2] + kk7*rtb[6] + kk8*rtb[10];
        m11 = kk6*rtb[3] + kk7*rtb[7] + kk8*rtb[11];
    }

    float px[PT], py[PT], pz[PT];
#pragma unroll
    for (int i = 0; i < PT; i++) {
        const float* pp = pts + (size_t)(pbase + 128*i) * 3;
        px[i] = pp[0]; py[i] = pp[1]; pz[i] = pp[2];
    }

    // ---- layer 1: acc = b1 + bilinear(F1) + fourier @ W1f  (j-quarter) ----
    ull acc[32];                   // acc[i*8 + q]: point i, outputs (jbase+2q, +1)
    INIT_BIAS(OFF_B1)

    BILIN(0); BILIN(1); BILIN(2); BILIN(3);

    // fourier features: sin/cos(2*pi*(p.Bg_m)) via exact fold + MUFU
    const float* bg = sm + OFF_BG;
#pragma unroll 1
    for (int m = 0; m < 64; m++) {
        float g0 = bg[3*m], g1 = bg[3*m+1], g2 = bg[3*m+2];
        ull sp[PT], cp[PT];
#pragma unroll
        for (int i = 0; i < PT; i++) {
            float t = px[i]*g0 + py[i]*g1 + pz[i]*g2;
            float s, c;
            sincos_2pi(t, &s, &c);
            sp[i] = pack2(s, s); cp[i] = pack2(c, c);
        }
        const ulonglong2* rs = (const ulonglong2*)(sm + OFF_W1F + m * 64 + jbase);
        const ulonglong2* rc = (const ulonglong2*)(sm + OFF_W1F + (64 + m) * 64 + jbase);
#pragma unroll
        for (int q = 0; q < 4; q++) {
            ulonglong2 ws = rs[q];
            ulonglong2 wc = rc[q];
#pragma unroll
            for (int i = 0; i < PT; i++) {
                acc[i*8 + 2*q]     = ffma2(sp[i], ws.x, acc[i*8 + 2*q]);
                acc[i*8 + 2*q + 1] = ffma2(sp[i], ws.y, acc[i*8 + 2*q + 1]);
                acc[i*8 + 2*q]     = ffma2(cp[i], wc.x, acc[i*8 + 2*q]);
                acc[i*8 + 2*q + 1] = ffma2(cp[i], wc.y, acc[i*8 + 2*q + 1]);
            }
        }
    }

    STORE_RELU();                 // h1 (this quarter) -> staging
    __syncthreads();              // all quarters must land before layer reads all k
    LAYER(OFF_W2, OFF_B2);        // h2 = relu(h1) @ W2 + b2   (j-quarter)
    __syncthreads();              // all reads of h1 staging done
    STORE_RELU();                 // h2 -> staging
    __syncthreads();
    LAYER(OFF_W3, OFF_B3);        // h3 = relu(h2) @ W3 + b3   (j-quarter)

    // final: partial dot over this quarter, then 4-way reduction via smem
    const float* w4 = sm + OFF_W4 + jbase;
    float o[PT] = {0.f, 0.f, 0.f, 0.f};
#pragma unroll
    for (int q = 0; q < 8; q++) {
        float wlo = w4[2*q], whi = w4[2*q+1];
#pragma unroll
        for (int i = 0; i < PT; i++) {
            float2 a = unpack2(acc[i*8 + q]);
            o[i] += fmaxf(a.x, 0.f) * wlo + fmaxf(a.y, 0.f) * whi;
        }
    }

    __syncthreads();              // staging free for reduction
#pragma unroll
    for (int i = 0; i < PT; i++)
        sm[OFF_ACT + jq * PPC + lh + 128*i] = o[i];   // rows 0..3 of staging
    __syncthreads();
    if (jq == 0) {
        float bias4 = __ldg(b4g);
#pragma unroll
        for (int i = 0; i < PT; i++) {
            int col = lh + 128*i;
            float r = sm[OFF_ACT + col] + sm[OFF_ACT + PPC + col]
                    + sm[OFF_ACT + 2*PPC + col] + sm[OFF_ACT + 3*PPC + col];
            out[pbase + 128*i] = r + bias4;
        }
    }
}

// ======================================================================
extern "C" void kernel_launch(void* const* d_in, const int* in_sizes, int n_in,
                              void* d_out, int out_size) {
    const float* features = (const float*)d_in[0];
    const float* points   = (const float*)d_in[1];
    const float* kmat     = (const float*)d_in[2];
    const float* rt       = (const float*)d_in[3];
    const float* Bg       = (const float*)d_in[4];
    const float* W1       = (const float*)d_in[5];
    const float* b1       = (const float*)d_in[6];
    const float* W2       = (const float*)d_in[7];
    const float* b2       = (const float*)d_in[8];
    const float* W3       = (const float*)d_in[9];
    const float* b3       = (const float*)d_in[10];
    const float* W4       = (const float*)d_in[11];
    const float* b4       = (const float*)d_in[12];
    float* out = (float*)d_out;

    cudaFuncSetAttribute(k_decoder, cudaFuncAttributeMaxDynamicSharedMemorySize, SMEM_BYTES);

    k_precompute<<<196, 128>>>(features, W1);
    k_decoder<<<(NBATCH * NPTS) / PPC, NT, SMEM_BYTES>>>(
        points, kmat, rt, Bg, W1, b1, W2, b2, W3, b3, W4, b4, out);
}